// round 8
// baseline (speedup 1.0000x reference)
#include <cuda_runtime.h>
#include <cuda_bf16.h>
#include <stdint.h>

#define N_EXPERTS 20
#define DIM 32
#define MAXB (1 << 17)     // 131072
#define TPB_B 256
#define TILE 128           // tokens per compute CTA
#define CTPB 128
#define ASTR 72            // tile row stride in bf16 elems (144B, conflict-free)

__device__ int g_cnt[N_EXPERTS];
__device__ int g_bucket[N_EXPERTS * MAXB];

// ---- kernel 1: fused bucket (warp-aggregated hist + claim + write) ------
__global__ void __launch_bounds__(TPB_B) k_bucket(const void* __restrict__ pos, int B) {
    __shared__ int sh[N_EXPERTS];
    __shared__ int sbase[N_EXPERTS];
    __shared__ int s_is64;

    if (threadIdx.x < N_EXPERTS) sh[threadIdx.x] = 0;
    if (threadIdx.x < 32) {
        // int64 pos => all odd 32-bit words are zero high-words (values < 20)
        int v = ((const int*)pos)[2 * threadIdx.x + 1];   // B >= 64 guaranteed
        unsigned nz = __ballot_sync(0xffffffffu, v != 0);
        if (threadIdx.x == 0) s_is64 = (nz == 0) ? 1 : 0;
    }
    __syncthreads();

    int t = blockIdx.x * TPB_B + threadIdx.x;
    bool valid = (t < B);
    int e = valid
          ? (s_is64 ? (int)((const long long*)pos)[t] : ((const int*)pos)[t])
          : -1;

    unsigned mm = __match_any_sync(0xffffffffu, e);
    int lane = threadIdx.x & 31;
    int rank = __popc(mm & ((1u << lane) - 1));
    int leader = __ffs(mm) - 1;
    int wbase = 0;
    if (lane == leader && valid) wbase = atomicAdd(&sh[e], __popc(mm));
    wbase = __shfl_sync(0xffffffffu, wbase, leader);
    int r = wbase + rank;

    __syncthreads();
    if (threadIdx.x < N_EXPERTS) {
        int c = sh[threadIdx.x];
        sbase[threadIdx.x] = c ? atomicAdd(&g_cnt[threadIdx.x], c) : 0;
    }
    __syncthreads();
    if (valid) g_bucket[e * MAXB + sbase[e] + r] = t;
}

// ---- mma / ldmatrix wrappers ----------------------------------------------
__device__ __forceinline__ void mma16816(float* c, const uint32_t* a, const uint32_t* b) {
    asm volatile(
        "mma.sync.aligned.m16n8k16.row.col.f32.bf16.bf16.f32 "
        "{%0,%1,%2,%3}, {%4,%5,%6,%7}, {%8,%9}, {%0,%1,%2,%3};"
        : "+f"(c[0]), "+f"(c[1]), "+f"(c[2]), "+f"(c[3])
        : "r"(a[0]), "r"(a[1]), "r"(a[2]), "r"(a[3]), "r"(b[0]), "r"(b[1]));
}
__device__ __forceinline__ void ldsm_x4(uint32_t* d, uint32_t addr) {
    asm volatile("ldmatrix.sync.aligned.m8n8.x4.shared.b16 {%0,%1,%2,%3}, [%4];"
                 : "=r"(d[0]), "=r"(d[1]), "=r"(d[2]), "=r"(d[3]) : "r"(addr));
}
__device__ __forceinline__ uint32_t smem_u32(const void* p) {
    uint32_t a;
    asm("{ .reg .u64 t; cvta.to.shared.u64 t, %1; cvt.u32.u64 %0, t; }" : "=r"(a) : "l"(p));
    return a;
}
// split fp32 pair into hi/lo bf16x2
__device__ __forceinline__ void split2(float a, float b, uint32_t& hi, uint32_t& lo) {
    __nv_bfloat162 hp = __floats2bfloat162_rn(a, b);
    float ra = a - __bfloat162float(hp.x);
    float rb = b - __bfloat162float(hp.y);
    __nv_bfloat162 lp = __floats2bfloat162_rn(ra, rb);
    hi = *reinterpret_cast<uint32_t*>(&hp);
    lo = *reinterpret_cast<uint32_t*>(&lp);
}
__device__ __forceinline__ uint32_t pkbf(float a, float b) {
    __nv_bfloat162 p = __floats2bfloat162_rn(a, b);
    return *reinterpret_cast<uint32_t*>(&p);
}
__device__ __forceinline__ float bfres(float a) {
    return a - __bfloat162float(__float2bfloat16(a));
}

// ---- kernel 2: HMMA compute (ldmatrix + register-resident h) -------------
__global__ void __launch_bounds__(CTPB) k_compute(
    const float* __restrict__ x,
    const float* __restrict__ W1, const float* __restrict__ b1,
    const float* __restrict__ W0, const float* __restrict__ b0,
    float* __restrict__ out)
{
    __shared__ __align__(16) __nv_bfloat16 sA[TILE * ASTR];      // 18432 B
    __shared__ __align__(16) __nv_bfloat16 sB1[DIM * ASTR];      // 4608 B
    __shared__ __align__(16) __nv_bfloat16 sB2[DIM * ASTR];      // 4608 B
    __shared__ __align__(16) float sb1[DIM], sb0[DIM];
    __shared__ int sTok[TILE];

    // ---- block -> (expert, tile) ----
    int rem = blockIdx.x;
    int e = 0, n = 0;
    #pragma unroll 1
    for (e = 0; e < N_EXPERTS; e++) {
        n = g_cnt[e];
        int nb = (n + TILE - 1) / TILE;
        if (rem < nb) break;
        rem -= nb;
    }
    if (e == N_EXPERTS) return;   // block-uniform, before any sync
    int base = rem * TILE;
    int tid = threadIdx.x;

    // ---- stage weights (hi/lo split) + biases ----
    #pragma unroll 1
    for (int i = tid; i < DIM * DIM; i += CTPB) {
        int o = i >> 5, k = i & 31;
        float w1v = W1[e * DIM * DIM + i];
        __nv_bfloat16 h1 = __float2bfloat16(w1v);
        sB1[o * ASTR + k]      = h1;
        sB1[o * ASTR + 32 + k] = __float2bfloat16(w1v - __bfloat162float(h1));
        float w0v = W0[e * DIM * DIM + i];
        __nv_bfloat16 h0 = __float2bfloat16(w0v);
        sB2[o * ASTR + k]      = h0;
        sB2[o * ASTR + 32 + k] = __float2bfloat16(w0v - __bfloat162float(h0));
    }
    if (tid < DIM) {
        sb1[tid] = b1[e * DIM + tid];
        sb0[tid] = b0[e * DIM + tid];
    }

    // ---- gather token row, split hi/lo into A tile (vectorized STS.128) ----
    int slot = base + tid;
    int tok = (slot < n) ? g_bucket[e * MAXB + slot] : -1;
    sTok[tid] = tok;
    {
        float v[DIM];
        #pragma unroll
        for (int j = 0; j < DIM; j++) v[j] = 0.0f;
        if (tok >= 0) {
            const float4* xp = (const float4*)(x + (size_t)tok * DIM);
            #pragma unroll
            for (int j = 0; j < DIM / 4; j++) {
                float4 q = xp[j];
                v[4*j+0] = q.x; v[4*j+1] = q.y; v[4*j+2] = q.z; v[4*j+3] = q.w;
            }
        }
        uint32_t rw[32];
        #pragma unroll
        for (int j = 0; j < 16; j++) split2(v[2*j], v[2*j+1], rw[j], rw[16 + j]);
        uint4* rp = (uint4*)(sA + tid * ASTR);
        #pragma unroll
        for (int q = 0; q < 8; q++)
            rp[q] = make_uint4(rw[4*q], rw[4*q+1], rw[4*q+2], rw[4*q+3]);
    }
    __syncthreads();

    // ---- fragment geometry / ldmatrix lane addressing ----
    int w  = tid >> 5;
    int l  = tid & 31;
    int g  = l >> 2;           // 0..7
    int t4 = l & 3;            // 0..3
    int lt = l >> 3;           // ldmatrix tile id 0..3
    int lr = l & 7;            // row within tile

    uint32_t sA_u  = smem_u32(sA);
    uint32_t sB1_u = smem_u32(sB1);
    uint32_t sB2_u = smem_u32(sB2);
    // A: tile0 rows m0..m0+7 (k lo8), tile1 rows +8 (k lo8), tile2/3 same rows k hi8
    uint32_t aBase[2];
    #pragma unroll
    for (int mt = 0; mt < 2; mt++)
        aBase[mt] = sA_u + (uint32_t)((32*w + 16*mt + (lt & 1) * 8 + lr) * (ASTR*2) + (lt >> 1) * 16);
    // B: tiles (n0-7,klo),(n0-7,khi),(n8-15,klo),(n8-15,khi)
    uint32_t bLane = (uint32_t)((((lt >> 1) * 8) + lr) * (ASTR*2) + (lt & 1) * 16);

    // layer 1 segment tables (elem16 units, *32 bytes):
    // products: Ahi.Bhi(k0,k1), Alo.Bhi(k0,k1), Ahi.Blo(k0,k1)
    const int jA[6] = {0, 1, 2, 3, 0, 1};
    const int jB[6] = {0, 1, 0, 1, 2, 3};
    // layer 0 B segments: Hh.Bhi(k0,k1), Hh.Blo(k0,k1), Hl.Bhi(k0,k1)
    const int jB0[6] = {0, 1, 2, 3, 0, 1};

    float acc[2][4][4];

    // ======================= layer 1 =======================
    #pragma unroll
    for (int mt = 0; mt < 2; mt++)
        #pragma unroll
        for (int nt = 0; nt < 4; nt++) {
            float2 bv = *(const float2*)&sb1[nt * 8 + 2 * t4];
            acc[mt][nt][0] = bv.x; acc[mt][nt][1] = bv.y;
            acc[mt][nt][2] = bv.x; acc[mt][nt][3] = bv.y;
        }
    #pragma unroll
    for (int ks = 0; ks < 6; ks++) {
        uint32_t bf[2][4];
        ldsm_x4(bf[0], sB1_u + bLane +        jB[ks] * 32);
        ldsm_x4(bf[1], sB1_u + bLane + 2304 + jB[ks] * 32);   // +16 rows * 144B
        #pragma unroll
        for (int mt = 0; mt < 2; mt++) {
            uint32_t af[4];
            ldsm_x4(af, aBase[mt] + jA[ks] * 32);
            mma16816(acc[mt][0], af, &bf[0][0]);
            mma16816(acc[mt][1], af, &bf[0][2]);
            mma16816(acc[mt][2], af, &bf[1][0]);
            mma16816(acc[mt][3], af, &bf[1][2]);
        }
    }

    // ---- h -> register A-frags (hi/lo), no smem round trip ----
    // D-frag layout == A-frag layout: kseg j from acc[mt][2j], acc[mt][2j+1]
    uint32_t Hh[2][2][4], Hl[2][2][4];
    #pragma unroll
    for (int mt = 0; mt < 2; mt++)
        #pragma unroll
        for (int j = 0; j < 2; j++) {
            const float* a0 = acc[mt][2*j];
            const float* a1 = acc[mt][2*j + 1];
            Hh[mt][j][0] = pkbf(a0[0], a0[1]);
            Hh[mt][j][1] = pkbf(a0[2], a0[3]);
            Hh[mt][j][2] = pkbf(a1[0], a1[1]);
            Hh[mt][j][3] = pkbf(a1[2], a1[3]);
            Hl[mt][j][0] = pkbf(bfres(a0[0]), bfres(a0[1]));
            Hl[mt][j][1] = pkbf(bfres(a0[2]), bfres(a0[3]));
            Hl[mt][j][2] = pkbf(bfres(a1[0]), bfres(a1[1]));
            Hl[mt][j][3] = pkbf(bfres(a1[2]), bfres(a1[3]));
        }

    // ======================= layer 0 =======================
    #pragma unroll
    for (int mt = 0; mt < 2; mt++)
        #pragma unroll
        for (int nt = 0; nt < 4; nt++) {
            float2 bv = *(const float2*)&sb0[nt * 8 + 2 * t4];
            acc[mt][nt][0] = bv.x; acc[mt][nt][1] = bv.y;
            acc[mt][nt][2] = bv.x; acc[mt][nt][3] = bv.y;
        }
    // products: (Hh0,Bhi0),(Hh1,Bhi1),(Hh0,Blo0),(Hh1,Blo1),(Hl0,Bhi0),(Hl1,Bhi1)
    #pragma unroll
    for (int p = 0; p < 6; p++) {
        int aj = p & 1;
        uint32_t bf[2][4];
        ldsm_x4(bf[0], sB2_u + bLane +        jB0[p] * 32);
        ldsm_x4(bf[1], sB2_u + bLane + 2304 + jB0[p] * 32);
        #pragma unroll
        for (int mt = 0; mt < 2; mt++) {
            const uint32_t* af = (p < 4) ? Hh[mt][aj] : Hl[mt][aj];
            mma16816(acc[mt][0], af, &bf[0][0]);
            mma16816(acc[mt][1], af, &bf[0][2]);
            mma16816(acc[mt][2], af, &bf[1][0]);
            mma16816(acc[mt][3], af, &bf[1][2]);
        }
    }

    // ---- epilogue: row sum-of-squares (4-lane bfly), normalize, store ----
    #pragma unroll
    for (int mt = 0; mt < 2; mt++) {
        int r0 = w * 32 + mt * 16 + g;
        float s0 = 0.0f, s1 = 0.0f;
        #pragma unroll
        for (int nt = 0; nt < 4; nt++) {
            s0 = fmaf(acc[mt][nt][0], acc[mt][nt][0], s0);
            s0 = fmaf(acc[mt][nt][1], acc[mt][nt][1], s0);
            s1 = fmaf(acc[mt][nt][2], acc[mt][nt][2], s1);
            s1 = fmaf(acc[mt][nt][3], acc[mt][nt][3], s1);
        }
        s0 += __shfl_xor_sync(0xffffffffu, s0, 1);
        s0 += __shfl_xor_sync(0xffffffffu, s0, 2);
        s1 += __shfl_xor_sync(0xffffffffu, s1, 1);
        s1 += __shfl_xor_sync(0xffffffffu, s1, 2);
        float inv0 = 1.0f / fmaxf(sqrtf(s0), 1e-12f);
        float inv1 = 1.0f / fmaxf(sqrtf(s1), 1e-12f);

        int tok0 = sTok[r0];
        int tok1 = sTok[r0 + 8];
        #pragma unroll
        for (int nt = 0; nt < 4; nt++) {
            int c = nt * 8 + 2 * t4;
            if (tok0 >= 0) {
                float2 v = make_float2(acc[mt][nt][0] * inv0, acc[mt][nt][1] * inv0);
                *(float2*)(out + (size_t)tok0 * DIM + c) = v;
            }
            if (tok1 >= 0) {
                float2 v = make_float2(acc[mt][nt][2] * inv1, acc[mt][nt][3] * inv1);
                *(float2*)(out + (size_t)tok1 * DIM + c) = v;
            }
        }
    }
}

// ---------------- launch -------------------------------------------------
extern "C" void kernel_launch(void* const* d_in, const int* in_sizes, int n_in,
                              void* d_out, int out_size) {
    const float* x  = (const float*)d_in[0];
    const float* W1 = (const float*)d_in[1];
    const float* b1 = (const float*)d_in[2];
    const float* W0 = (const float*)d_in[3];
    const float* b0 = (const float*)d_in[4];
    const void*  pos = d_in[5];
    float* out = (float*)d_out;

    int B = in_sizes[0] / DIM;
    if (B > MAXB) B = MAXB;
    int nblk_b = (B + TPB_B - 1) / TPB_B;
    int nblk_c = (B + TILE - 1) / TILE + N_EXPERTS - 1;

    void* cnt_ptr = nullptr;
    cudaGetSymbolAddress(&cnt_ptr, g_cnt);
    cudaMemsetAsync(cnt_ptr, 0, N_EXPERTS * sizeof(int), 0);

    k_bucket<<<nblk_b, TPB_B>>>(pos, B);
    k_compute<<<nblk_c, CTPB>>>(x, W1, b1, W0, b0, out);
}